// round 17
// baseline (speedup 1.0000x reference)
#include <cuda_runtime.h>
#include <cuda_bf16.h>
#include <cstddef>
#include <cstdint>

// Problem constants
#define SS 2048
#define BB 64
#define DD 128
#define HH 128
#define GG 512   // 4*H

// 256 MB scratch for precomputed input gates: pre[t][b][512] = x@W_ih^T + b
__device__ float g_pre[(size_t)SS * BB * GG];

typedef unsigned long long ull;

// Packed fp32x2 ops (sm_100+)
#define FMA_F32X2(d, a, b, c) \
    asm("fma.rn.f32x2 %0, %1, %2, %3;" : "=l"(d) : "l"(a), "l"(b), "l"(c))
#define ADD_F32X2(d, a, b) \
    asm("add.rn.f32x2 %0, %1, %2;" : "=l"(d) : "l"(a), "l"(b))
#define UNPACK2(lo, hi, in) \
    asm("mov.b64 {%0, %1}, %2;" : "=f"(lo), "=f"(hi) : "l"(in))
// Single-instruction tanh (MUFU.TANH, sm_75+)
#define TANH_APPROX(d, x) \
    asm("tanh.approx.f32 %0, %1;" : "=f"(d) : "f"(x))
// fp32 -> tf32 bits (round to nearest)
#define CVT_TF32(out, in) \
    asm("cvt.rna.tf32.f32 %0, %1;" : "=r"(out) : "f"(in))

// ---------------------------------------------------------------------------
// Kernel P: pre = X @ W_ih^T + bias via tf32 mma.sync.m16n8k8.
// R16 winner, unchanged: 256x128 tiles, 512 threads (16 warps x 16 rows).
// ---------------------------------------------------------------------------
__global__ void __launch_bounds__(512) pre_gemm_kernel(
    const float* __restrict__ X,
    const float* __restrict__ Wih,
    const float* __restrict__ bias)
{
    extern __shared__ uint32_t smP[];
    uint32_t* As = smP;                 // 32768 u32 = 128 KB
    uint32_t* Bs = smP + 32768;         // 16384 u32 = 64 KB

    const int tid  = threadIdx.x;
    const int row0 = blockIdx.x * 256;
    const int col0 = blockIdx.y * 128;

    #pragma unroll
    for (int it = 0; it < 64; it++) {
        int idx = it * 512 + tid;
        int m = idx >> 7;
        int k = idx & 127;
        float v = X[(size_t)(row0 + m) * DD + k];
        uint32_t tv;
        CVT_TF32(tv, v);
        int w    = m >> 4, mr = m & 15;
        int k8   = k >> 3, kc = k & 7;
        int lane = ((mr & 7) << 2) | (kc & 3);
        int j    = (mr >> 3) | ((kc >> 2) << 1);
        As[(((w * 16 + k8) * 32) + lane) * 4 + j] = tv;
    }
    #pragma unroll
    for (int it = 0; it < 32; it++) {
        int idx = it * 512 + tid;
        int n = idx >> 7;
        int k = idx & 127;
        float v = Wih[(size_t)(col0 + n) * DD + k];
        uint32_t tv;
        CVT_TF32(tv, v);
        int n8   = n >> 3, nc = n & 7;
        int k8   = k >> 3, kc = k & 7;
        int lane = (nc << 2) | (kc & 3);
        int j    = kc >> 2;
        Bs[(((n8 * 16 + k8) * 32) + lane) * 2 + j] = tv;
    }
    __syncthreads();

    const int warp = tid >> 5;
    const int lane = tid & 31;

    float c[16][4];
    #pragma unroll
    for (int n8 = 0; n8 < 16; n8++)
        #pragma unroll
        for (int j = 0; j < 4; j++) c[n8][j] = 0.0f;

    #pragma unroll 1
    for (int k8 = 0; k8 < 16; k8++) {
        uint4 af = *(const uint4*)&As[(((warp * 16 + k8) * 32) + lane) * 4];
        #pragma unroll
        for (int n8 = 0; n8 < 16; n8++) {
            uint2 bf = *(const uint2*)&Bs[(((n8 * 16 + k8) * 32) + lane) * 2];
            asm("mma.sync.aligned.m16n8k8.row.col.f32.tf32.tf32.f32 "
                "{%0,%1,%2,%3}, {%4,%5,%6,%7}, {%8,%9}, {%0,%1,%2,%3};"
                : "+f"(c[n8][0]), "+f"(c[n8][1]), "+f"(c[n8][2]), "+f"(c[n8][3])
                : "r"(af.x), "r"(af.y), "r"(af.z), "r"(af.w),
                  "r"(bf.x), "r"(bf.y));
        }
    }

    const int ra = row0 + warp * 16 + (lane >> 2);
    const int cb = 2 * (lane & 3);
    #pragma unroll
    for (int n8 = 0; n8 < 16; n8++) {
        int col = col0 + n8 * 8 + cb;
        float2 bv = *(const float2*)&bias[col];
        float2 v0 = make_float2(c[n8][0] + bv.x, c[n8][1] + bv.y);
        float2 v1 = make_float2(c[n8][2] + bv.x, c[n8][3] + bv.y);
        *(float2*)&g_pre[(size_t)ra * GG + col]       = v0;
        *(float2*)&g_pre[(size_t)(ra + 8) * GG + col] = v1;
    }
}

// ---------------------------------------------------------------------------
// Cluster helpers
// ---------------------------------------------------------------------------
__device__ __forceinline__ uint32_t smem_u32(const void* p) {
    uint32_t a;
    asm("{ .reg .u64 t; cvta.to.shared.u64 t, %1; cvt.u32.u64 %0, t; }"
        : "=r"(a) : "l"(p));
    return a;
}
__device__ __forceinline__ uint32_t my_ctarank() {
    uint32_t r;
    asm("mov.u32 %0, %%cluster_ctarank;" : "=r"(r));
    return r;
}
__device__ __forceinline__ uint32_t mapa_u32(uint32_t local, uint32_t rank) {
    uint32_t r;
    asm("mapa.shared::cluster.u32 %0, %1, %2;" : "=r"(r) : "r"(local), "r"(rank));
    return r;
}
__device__ __forceinline__ void mbar_init(uint32_t addr, uint32_t count) {
    asm volatile("mbarrier.init.shared.b64 [%0], %1;"
                 :: "r"(addr), "r"(count) : "memory");
}
// Async store with HW transaction tracking (data + signal, no fences).
__device__ __forceinline__ void st_async_f32(uint32_t dst, float v, uint32_t mbar) {
    asm volatile(
        "st.async.shared::cluster.mbarrier::complete_tx::bytes.b32 [%0], %1, [%2];"
        :: "r"(dst), "r"(__float_as_uint(v)), "r"(mbar) : "memory");
}
__device__ __forceinline__ void mbar_expect_tx(uint32_t mbar, uint32_t bytes) {
    asm volatile("mbarrier.arrive.expect_tx.shared.b64 _, [%0], %1;"
                 :: "r"(mbar), "r"(bytes) : "memory");
}
__device__ __forceinline__ void mbar_wait(uint32_t mbar, uint32_t parity) {
    asm volatile(
        "{\n\t"
        ".reg .pred P;\n"
        "WL_%=:\n\t"
        "mbarrier.try_wait.parity.acquire.cta.shared::cta.b64 P, [%0], %1, 0x989680;\n\t"
        "@P bra WD_%=;\n\t"
        "bra WL_%=;\n"
        "WD_%=:\n\t"
        "}"
        :: "r"(mbar), "r"(parity) : "memory");
}
__device__ __forceinline__ void cluster_sync_hw() {
    asm volatile("barrier.cluster.arrive.aligned;" ::: "memory");
    asm volatile("barrier.cluster.wait.aligned;" ::: "memory");
}

// ---------------------------------------------------------------------------
// Kernel R (R17): reverse scan, 2-CTA cluster per batch, PAIR-INTERLEAVED
// gate mapping. Thread (q = tid&1, k = tid>>1); rank0 lane-pairs own
// (i[k], f[k]), rank1 own (g[k], o[k]) — gate row = rank*256 + 128*q + k.
// Local pair acts exchange via 2 SHFL (same warp, adjacent lanes); peer
// pair arrives as adjacent floats act_recv[m][2k..2k+1] -> one LDS.64.
// No local STS, no pre-wait barrier. Both lanes (and both CTAs) compute
// the combine redundantly (bit-identical); even lanes write h/out.
// mbar protocol identical to R10: ping-pong, expect 1024 B, re-arm s+2.
// ---------------------------------------------------------------------------
__global__ void __launch_bounds__(256, 1) __cluster_dims__(2, 1, 1)
lstm_rev_cluster_kernel(
    const float* __restrict__ timeArr,   // [S*B]
    const float* __restrict__ Whh,       // [512,128]
    const float* __restrict__ w_t,       // [128]
    const float* __restrict__ b_t,       // [128]
    float* __restrict__ out)             // outputs ++ h ++ c
{
    __shared__ __align__(16) float hbuf[2][128];
    __shared__ __align__(8) float act_recv[2][256];   // peer pair acts
    __shared__ ull mbars[2];

    const int tid   = threadIdx.x;
    const uint32_t rank  = my_ctarank();
    const uint32_t prank = 1u - rank;
    const int batch = blockIdx.x >> 1;
    const int q     = tid & 1;                 // pair member
    const int k     = tid >> 1;                // h index 0..127
    const int grow  = (int)rank * 256 + 128 * q + k;   // gate row

    // ALL weights register-resident: 64 ull = 128 floats
    ull wR[64];
    {
        const ull* wp = (const ull*)(Whh + (size_t)grow * HH);
        #pragma unroll
        for (int c = 0; c < 64; c++) wR[c] = wp[c];
    }

    // Cluster-space addresses: my pair slot in PEER's act_recv + peer mbars
    const uint32_t mb0_l = smem_u32(&mbars[0]);
    const uint32_t mb1_l = smem_u32(&mbars[1]);
    uint32_t dst_peer[2], mb_peer[2];
    #pragma unroll
    for (int m = 0; m < 2; m++) {
        dst_peer[m] = mapa_u32(smem_u32(&act_recv[m][2 * k + q]), prank);
        mb_peer[m]  = mapa_u32((m == 0) ? mb0_l : mb1_l, prank);
    }

    if (tid == 0) {
        mbar_init(mb0_l, 1);
        mbar_init(mb1_l, 1);
        // pre-arm for steps 0 and 1 (peer's 256 floats each)
        mbar_expect_tx(mb0_l, 1024);
        mbar_expect_tx(mb1_l, 1024);
    }
    if (tid < 128) hbuf[0][tid] = 0.0f;

    const float wt = w_t[k];
    const float bt = b_t[k];
    float creg = 0.0f, hlast = 0.0f;

    __syncthreads();
    cluster_sync_hw();   // mbars init+armed visible cluster-wide

    const float* preP = g_pre + (size_t)batch * GG + grow;

    // depth-2 prefetch pipeline for pre/tv
    float pre_n1 = preP[(size_t)(SS - 1) * BB * GG];
    float tv_n1  = timeArr[(size_t)(SS - 1) * BB + batch];
    float pre_n2 = preP[(size_t)(SS - 2) * BB * GG];
    float tv_n2  = timeArr[(size_t)(SS - 2) * BB + batch];

    // g-gate = rank1,q0 uses tanh(x); others sigmoid = 0.5*tanh(x/2)+0.5
    const bool  is_g    = (rank == 1) && (q == 0);
    const float pre_mul = is_g ? 1.0f : 0.5f;
    const unsigned lb   = (tid & 31) & ~1u;    // pair base lane
    const unsigned FULL = 0xffffffffu;

    for (int s = 0; s < SS; s++) {
        const int t   = SS - 1 - s;
        const int cur = s & 1;
        const int m   = s & 1;
        const uint32_t par = (uint32_t)((s >> 1) & 1);

        const float pre_j = pre_n1;
        const float tv    = tv_n1;
        pre_n1 = pre_n2;
        tv_n1  = tv_n2;
        if (t >= 2) {   // prefetch two steps ahead
            pre_n2 = preP[(size_t)(t - 2) * BB * GG];
            tv_n2  = timeArr[(size_t)(t - 2) * BB + batch];
        }

        // dot: gates[grow] = pre + W_hh[grow].h  (weights in regs)
        const ulonglong2* h2 = (const ulonglong2*)&hbuf[cur][0];
        ull ac[8];
        #pragma unroll
        for (int i = 0; i < 8; i++) ac[i] = 0ULL;
        #pragma unroll
        for (int i = 0; i < 8; i++) {
            ulonglong2 hva = h2[4 * i],     hvb = h2[4 * i + 1];
            ulonglong2 hvc = h2[4 * i + 2], hvd = h2[4 * i + 3];
            FMA_F32X2(ac[0], wR[8 * i],     hva.x, ac[0]);
            FMA_F32X2(ac[1], wR[8 * i + 1], hva.y, ac[1]);
            FMA_F32X2(ac[2], wR[8 * i + 2], hvb.x, ac[2]);
            FMA_F32X2(ac[3], wR[8 * i + 3], hvb.y, ac[3]);
            FMA_F32X2(ac[4], wR[8 * i + 4], hvc.x, ac[4]);
            FMA_F32X2(ac[5], wR[8 * i + 5], hvc.y, ac[5]);
            FMA_F32X2(ac[6], wR[8 * i + 6], hvd.x, ac[6]);
            FMA_F32X2(ac[7], wR[8 * i + 7], hvd.y, ac[7]);
        }
        ADD_F32X2(ac[0], ac[0], ac[1]);
        ADD_F32X2(ac[2], ac[2], ac[3]);
        ADD_F32X2(ac[4], ac[4], ac[5]);
        ADD_F32X2(ac[6], ac[6], ac[7]);
        ADD_F32X2(ac[0], ac[0], ac[2]);
        ADD_F32X2(ac[4], ac[4], ac[6]);
        ADD_F32X2(ac[0], ac[0], ac[4]);
        float lo, hi;
        UNPACK2(lo, hi, ac[0]);
        float gsum = pre_j + (lo + hi);

        // activation via single MUFU.TANH
        float th;
        TANH_APPROX(th, pre_mul * gsum);
        float a = is_g ? th : fmaf(0.5f, th, 0.5f);

        // send my act to the PEER's pair slot (HW tx tracking)
        st_async_f32(dst_peer[m], a, mb_peer[m]);

        // exchange within the lane pair (same warp, no barrier)
        float aE = __shfl_sync(FULL, a, lb);        // even-lane act
        float aO = __shfl_sync(FULL, a, lb + 1);    // odd-lane act

        // decay term hoisted off the post-wait critical path
        float dec = __expf(-fmaxf(tv * wt + bt, 0.0f));
        float cfd = creg * dec;

        mbar_wait(m ? mb1_l : mb0_l, par);  // peer pair acts visible
        if (tid == 0)  // re-arm for step s+2 (ordered before s+1 sends by
            mbar_expect_tx(m ? mb1_l : mb0_l, 1024);  // the end-of-step bar)

        // one LDS.64: peer's (even, odd) acts for this h index
        float2 pr = *(const float2*)&act_recv[m][2 * k];

        // map to i,f,g,o: rank0 local=(i,f), peer=(g,o); rank1 mirrored
        float iv = rank ? pr.x : aE;
        float fv = rank ? pr.y : aO;
        float gv = rank ? aE   : pr.x;
        float ov = rank ? aO   : pr.y;

        creg = fv * cfd + iv * gv;
        float tc;
        TANH_APPROX(tc, creg);
        float hv = ov * tc;
        hlast = hv;

        if (q == 0) {
            hbuf[cur ^ 1][k] = hv;
            out[(size_t)t * (BB * HH) + (size_t)batch * HH + k] = hv;
        }
        __syncthreads();   // h published; also orders re-arm before s+1 sends
    }

    // final state: h then c after the outputs block (rank0 even lanes)
    if (rank == 0 && q == 0) {
        size_t base = (size_t)SS * BB * HH;
        out[base + (size_t)batch * HH + k] = hlast;
        out[base + (size_t)BB * HH + (size_t)batch * HH + k] = creg;
    }

    cluster_sync_hw();   // no early exit while peer ops in flight
}

// ---------------------------------------------------------------------------
// Launch
// ---------------------------------------------------------------------------
extern "C" void kernel_launch(void* const* d_in, const int* in_sizes, int n_in,
                              void* d_out, int out_size)
{
    const float* X    = (const float*)d_in[0];  // input  (S,B,D)
    const float* Tm   = (const float*)d_in[1];  // time   (S,B,1)
    const float* Wih  = (const float*)d_in[2];  // (4H, D)
    const float* Whh  = (const float*)d_in[3];  // (4H, H)
    const float* bias = (const float*)d_in[4];  // (4H,)
    const float* wt   = (const float*)d_in[5];  // (H,)
    const float* bt   = (const float*)d_in[6];  // (H,)
    float* out = (float*)d_out;

    const int smemP = (32768 + 16384) * (int)sizeof(uint32_t);   // 196608 B
    cudaFuncSetAttribute(pre_gemm_kernel,
                         cudaFuncAttributeMaxDynamicSharedMemorySize, smemP);

    // 256-row tiles: grid (512, 4), 512 threads
    dim3 gridP((SS * BB) / 256, GG / 128);
    pre_gemm_kernel<<<gridP, 512, smemP>>>(X, Wih, bias);

    // 64 clusters of 2 CTAs (grid 128), 256 threads each
    lstm_rev_cluster_kernel<<<BB * 2, 256>>>(Tm, Whh, wt, bt, out);
}